// round 3
// baseline (speedup 1.0000x reference)
#include <cuda_runtime.h>
#include <math.h>

#define B_ 2
#define T_ 2048
#define E_ 2048
#define G_ 4
#define QPG_ 4
#define D_ 128
#define H_ (G_*QPG_)    // 16
#define NQ_ (H_*D_)     // 2048
#define NKV_ (2*G_*D_)  // 1024
#define M_ (B_*T_)      // 4096

// Scratch (no cudaMalloc allowed): q, kv, attn_out
__device__ float g_q[(size_t)M_ * NQ_];     // 33.5 MB
__device__ float g_kv[(size_t)M_ * NKV_];   // 16.8 MB
__device__ float g_att[(size_t)M_ * NQ_];   // 33.5 MB

// ---------------------------------------------------------------------------
// Generic fp32 GEMM: C[M,N] = A[M,K] @ W[K,N] (+ bias). Tiles 64x64x16,
// 256 threads, 4x4 microtile. A stored k-major in smem so the inner loop is
// two LDS.128 + 16 FMA per k.
// ---------------------------------------------------------------------------
__global__ __launch_bounds__(256) void gemm_bias_kernel(
    const float* __restrict__ A, const float* __restrict__ W,
    const float* __restrict__ bias, float* __restrict__ C,
    int Msz, int Nsz, int Ksz)
{
    constexpr int BK = 16;
    __shared__ float Ast[BK][68];   // [k][m], padded
    __shared__ float Ws [BK][68];   // [k][n], padded

    const int tid = threadIdx.x;
    const int tx = tid & 15, ty = tid >> 4;
    const int m0 = blockIdx.y * 64, n0 = blockIdx.x * 64;

    const int arow = tid >> 2;            // 0..63
    const int akq  = (tid & 3) * 4;       // 0,4,8,12
    const int wrow = tid >> 4;            // 0..15
    const int wcg  = (tid & 15) * 4;      // 0..60

    float acc[4][4] = {};

    for (int k0 = 0; k0 < Ksz; k0 += BK) {
        float4 av = *(const float4*)&A[(size_t)(m0 + arow) * Ksz + k0 + akq];
        Ast[akq + 0][arow] = av.x;
        Ast[akq + 1][arow] = av.y;
        Ast[akq + 2][arow] = av.z;
        Ast[akq + 3][arow] = av.w;
        *(float4*)&Ws[wrow][wcg] =
            *(const float4*)&W[(size_t)(k0 + wrow) * Nsz + n0 + wcg];
        __syncthreads();

        #pragma unroll
        for (int kk = 0; kk < BK; kk++) {
            float4 a = *(const float4*)&Ast[kk][ty * 4];
            float4 b = *(const float4*)&Ws[kk][tx * 4];
            float ar[4] = {a.x, a.y, a.z, a.w};
            float br[4] = {b.x, b.y, b.z, b.w};
            #pragma unroll
            for (int i = 0; i < 4; i++)
                #pragma unroll
                for (int j = 0; j < 4; j++)
                    acc[i][j] = fmaf(ar[i], br[j], acc[i][j]);
        }
        __syncthreads();
    }

    #pragma unroll
    for (int i = 0; i < 4; i++) {
        int row = m0 + ty * 4 + i;
        int col = n0 + tx * 4;
        float4 o = make_float4(acc[i][0], acc[i][1], acc[i][2], acc[i][3]);
        if (bias) {
            o.x += bias[col + 0]; o.y += bias[col + 1];
            o.z += bias[col + 2]; o.w += bias[col + 3];
        }
        *(float4*)&C[(size_t)row * Nsz + col] = o;
    }
}

// ---------------------------------------------------------------------------
// Add sinusoidal PE into q (all 16 heads) and the K half of kv (4 groups).
// One block per (b,t), 128 threads = one per d.
// ---------------------------------------------------------------------------
__global__ __launch_bounds__(128) void add_pe_kernel(
    float* __restrict__ q, float* __restrict__ kv)
{
    int bt = blockIdx.x;
    int d  = threadIdx.x;
    int t  = bt % T_;
    int i2 = d & ~1;
    float inv = expf(-logf(10000.0f) * (float)i2 / (float)D_);
    float ang = (float)t * inv;
    float pe  = (d & 1) ? cosf(ang) : sinf(ang);

    float* qrow = q + (size_t)bt * NQ_;
    #pragma unroll
    for (int h = 0; h < H_; h++) qrow[h * D_ + d] += pe;

    float* kvrow = kv + (size_t)bt * NKV_;
    #pragma unroll
    for (int g = 0; g < G_; g++) kvrow[g * 2 * D_ + d] += pe;
}

// ---------------------------------------------------------------------------
// Flash attention, fp32. Block = (q-tile of 64 rows, (b,head)).
// Static smem (< 48KB): Qst[128][68] (d-major), Kst[128][68] (d-major,
// ALIASED by Ss[64][65] for the P tile after the S-GEMM has consumed K),
// Vs[64][132].
// 256 threads; S-gemm 4x4 microtile, PV 4x8 microtile; online softmax with
// per-row stats replicated across the 16 lanes that share ty.
// ---------------------------------------------------------------------------
__global__ __launch_bounds__(256) void attn_kernel(
    const float* __restrict__ q, const float* __restrict__ kv,
    float* __restrict__ out)
{
    __shared__ float Qst[128 * 68];
    __shared__ float Kst[128 * 68];   // also holds Ss[64][65] during PV phase
    __shared__ float Vs [64 * 132];
    float* Ss = Kst;                  // alias: S-GEMM is done with Kst before P is stored

    const int qt = blockIdx.x;
    const int bh = blockIdx.y;
    const int b = bh / H_, h = bh % H_, g = h / QPG_;
    const int q0 = qt * 64;

    const int tid = threadIdx.x;
    const int tx = tid & 15, ty = tid >> 4;
    const float scale = 0.088388347648318447f;   // 1/sqrt(128)

    // Load Q tile transposed (d-major)
    for (int it = tid; it < 64 * 32; it += 256) {
        int row = it >> 5;
        int dg  = (it & 31) * 4;
        float4 v = *(const float4*)&q[(size_t)(b * T_ + q0 + row) * NQ_ + h * D_ + dg];
        Qst[(dg + 0) * 68 + row] = v.x;
        Qst[(dg + 1) * 68 + row] = v.y;
        Qst[(dg + 2) * 68 + row] = v.z;
        Qst[(dg + 3) * 68 + row] = v.w;
    }

    float acc[4][8] = {};
    float mrun[4], lrun[4];
    #pragma unroll
    for (int i = 0; i < 4; i++) { mrun[i] = -INFINITY; lrun[i] = 0.0f; }

    for (int kt = 0; kt <= qt; kt++) {
        const int k0 = kt * 64;
        __syncthreads();   // previous PV done (and Q load on first iter)

        // Load K transposed + V row-major
        for (int it = tid; it < 64 * 32; it += 256) {
            int row = it >> 5;
            int dg  = (it & 31) * 4;
            const float* base = &kv[(size_t)(b * T_ + k0 + row) * NKV_ + g * 2 * D_];
            float4 kvv = *(const float4*)(base + dg);
            Kst[(dg + 0) * 68 + row] = kvv.x;
            Kst[(dg + 1) * 68 + row] = kvv.y;
            Kst[(dg + 2) * 68 + row] = kvv.z;
            Kst[(dg + 3) * 68 + row] = kvv.w;
            *(float4*)&Vs[row * 132 + dg] = *(const float4*)(base + D_ + dg);
        }
        __syncthreads();

        // S = Q @ K^T (4x4 per thread)
        float s[4][4] = {};
        #pragma unroll 4
        for (int d = 0; d < 128; d++) {
            float4 a  = *(const float4*)&Qst[d * 68 + ty * 4];
            float4 bv = *(const float4*)&Kst[d * 68 + tx * 4];
            float ar[4] = {a.x, a.y, a.z, a.w};
            float br[4] = {bv.x, bv.y, bv.z, bv.w};
            #pragma unroll
            for (int i = 0; i < 4; i++)
                #pragma unroll
                for (int j = 0; j < 4; j++)
                    s[i][j] = fmaf(ar[i], br[j], s[i][j]);
        }

        const bool diag = (kt == qt);
        #pragma unroll
        for (int i = 0; i < 4; i++)
            #pragma unroll
            for (int j = 0; j < 4; j++) {
                s[i][j] *= scale;
                if (diag && (tx * 4 + j) > (ty * 4 + i)) s[i][j] = -INFINITY;
            }

        // Online softmax update (stats replicated across the 16 lanes of ty)
        float cfix[4], nm[4];
        #pragma unroll
        for (int i = 0; i < 4; i++) {
            float lm = fmaxf(fmaxf(s[i][0], s[i][1]), fmaxf(s[i][2], s[i][3]));
            #pragma unroll
            for (int m = 8; m >= 1; m >>= 1)
                lm = fmaxf(lm, __shfl_xor_sync(0xffffffffu, lm, m));
            float newm = fmaxf(mrun[i], lm);
            cfix[i] = __expf(mrun[i] - newm);
            mrun[i] = newm;
            nm[i] = newm;
        }

        // All lanes are done reading Kst for this tile before Ss (=Kst) is
        // written: every thread finished its S-GEMM above, and the barrier
        // below orders P-stores against the next tile's K loads.
        __syncthreads();   // S-GEMM reads of Kst complete block-wide

        #pragma unroll
        for (int i = 0; i < 4; i++) {
            float ps = 0.0f;
            #pragma unroll
            for (int j = 0; j < 4; j++) {
                float p = __expf(s[i][j] - nm[i]);
                Ss[(ty * 4 + i) * 65 + tx * 4 + j] = p;
                ps += p;
            }
            #pragma unroll
            for (int m = 8; m >= 1; m >>= 1)
                ps += __shfl_xor_sync(0xffffffffu, ps, m);
            lrun[i] = lrun[i] * cfix[i] + ps;
            #pragma unroll
            for (int j = 0; j < 8; j++) acc[i][j] *= cfix[i];
        }
        __syncthreads();   // Ss visible

        // O += P @ V (rows ty*4+i, cols tx*8+j)
        #pragma unroll 2
        for (int s2 = 0; s2 < 64; s2++) {
            float p0 = Ss[(ty * 4 + 0) * 65 + s2];
            float p1 = Ss[(ty * 4 + 1) * 65 + s2];
            float p2 = Ss[(ty * 4 + 2) * 65 + s2];
            float p3 = Ss[(ty * 4 + 3) * 65 + s2];
            float4 v0 = *(const float4*)&Vs[s2 * 132 + tx * 8];
            float4 v1 = *(const float4*)&Vs[s2 * 132 + tx * 8 + 4];
            float vr[8] = {v0.x, v0.y, v0.z, v0.w, v1.x, v1.y, v1.z, v1.w};
            float pr[4] = {p0, p1, p2, p3};
            #pragma unroll
            for (int i = 0; i < 4; i++)
                #pragma unroll
                for (int j = 0; j < 8; j++)
                    acc[i][j] = fmaf(pr[i], vr[j], acc[i][j]);
        }
    }

    // Epilogue: divide by l, write out
    #pragma unroll
    for (int i = 0; i < 4; i++) {
        int row = q0 + ty * 4 + i;
        float inv_l = 1.0f / lrun[i];
        float* dst = out + (size_t)(b * T_ + row) * NQ_ + h * D_ + tx * 8;
        float4 o0 = make_float4(acc[i][0] * inv_l, acc[i][1] * inv_l,
                                acc[i][2] * inv_l, acc[i][3] * inv_l);
        float4 o1 = make_float4(acc[i][4] * inv_l, acc[i][5] * inv_l,
                                acc[i][6] * inv_l, acc[i][7] * inv_l);
        *(float4*)&dst[0] = o0;
        *(float4*)&dst[4] = o1;
    }
}

// ---------------------------------------------------------------------------
extern "C" void kernel_launch(void* const* d_in, const int* in_sizes, int n_in,
                              void* d_out, int out_size)
{
    const float* x   = (const float*)d_in[0];
    const float* wq  = (const float*)d_in[1];
    const float* bq  = (const float*)d_in[2];
    const float* wkv = (const float*)d_in[3];
    const float* bkv = (const float*)d_in[4];
    const float* wo  = (const float*)d_in[5];
    float* out = (float*)d_out;

    float *qbuf, *kvbuf, *attbuf;
    cudaGetSymbolAddress((void**)&qbuf,  g_q);
    cudaGetSymbolAddress((void**)&kvbuf, g_kv);
    cudaGetSymbolAddress((void**)&attbuf, g_att);

    dim3 blk(256);

    // Projections
    gemm_bias_kernel<<<dim3(NQ_ / 64, M_ / 64), blk>>>(x, wq, bq, qbuf, M_, NQ_, E_);
    gemm_bias_kernel<<<dim3(NKV_ / 64, M_ / 64), blk>>>(x, wkv, bkv, kvbuf, M_, NKV_, E_);

    // Positional encoding into q and k
    add_pe_kernel<<<M_, D_>>>(qbuf, kvbuf);

    // Flash attention (static smem < 48KB, no attribute calls needed)
    attn_kernel<<<dim3(T_ / 64, B_ * H_), blk>>>(qbuf, kvbuf, attbuf);

    // Output projection
    gemm_bias_kernel<<<dim3(E_ / 64, M_ / 64), blk>>>(attbuf, wo, nullptr, out, M_, E_, NQ_);
}